// round 13
// baseline (speedup 1.0000x reference)
#include <cuda_runtime.h>
#include <cuda_bf16.h>
#include <math.h>

#define B_  2
#define T_  512
#define H_  8
#define D_  64
#define E_  512
#define HD_ 512
#define BH_ 16
#define KK_ 64
#define M_  1024

typedef unsigned long long ull;

// ---------------- scratch ----------------
__device__ float g_Q [BH_ * T_ * D_];
__device__ float g_K0[BH_ * T_ * D_];
__device__ float g_K1[BH_ * T_ * D_];
__device__ float g_V0[BH_ * T_ * D_];
__device__ float g_V1[BH_ * T_ * D_];
__device__ float g_ctx[M_ * HD_];
__device__ float g_L[2 * BH_ * T_ * T_];    // causal logits, [r*16+bh][t][s]
__device__ int   g_idx0[BH_ * T_ * KK_];
__device__ int   g_idx1[BH_ * T_ * KK_];

// ---------------------------------------------------------------------------
// 0) zero d_out (split-K accumulator init)
// ---------------------------------------------------------------------------
__global__ __launch_bounds__(256)
void zero_kernel(float* __restrict__ out, int n4)
{
    int i = blockIdx.x * blockDim.x + threadIdx.x;
    if (i < n4) ((float4*)out)[i] = make_float4(0.f, 0.f, 0.f, 0.f);
}

// ---------------------------------------------------------------------------
// 1) Projections: 128x128 tile, 256 thr, 8x8 micro, BK=8, prefetch. grid(20,8)
// ---------------------------------------------------------------------------
#define ASTR 132
__global__ __launch_bounds__(256)
void proj_kernel(const float* __restrict__ x,
                 const float* __restrict__ Wq,
                 const float* __restrict__ Wk,
                 const float* __restrict__ Wv)
{
    const int bx = blockIdx.x;
    const int z  = bx >> 2;
    const int nb = (bx & 3) * 128;
    const int m0 = blockIdx.y * 128;

    const float* Bm = (z == 0) ? Wq
                    : (z <= 2) ? (Wk + (z - 1) * (E_ * HD_))
                               : (Wv + (z - 3) * (E_ * HD_));
    float* C = (z == 0) ? g_Q : (z == 1) ? g_K0 : (z == 2) ? g_K1
             : (z == 3) ? g_V0 : g_V1;

    const int tid = threadIdx.x;
    const int tx = tid & 15, ty = tid >> 4;

    __shared__ float As[8][ASTR];
    __shared__ float Bs[8][128];

    const int am = tid >> 1, akp = (tid & 1) * 4;
    const int brow = tid >> 5, bch = (tid & 31) * 4;

    float acc[8][8];
    #pragma unroll
    for (int i = 0; i < 8; i++)
        #pragma unroll
        for (int j = 0; j < 8; j++) acc[i][j] = 0.f;

    float4 ra = *(const float4*)(x + (m0 + am) * E_ + akp);
    float4 rb = *(const float4*)(Bm + brow * HD_ + nb + bch);

    for (int k0 = 0; k0 < E_; k0 += 8) {
        As[akp + 0][am] = ra.x; As[akp + 1][am] = ra.y;
        As[akp + 2][am] = ra.z; As[akp + 3][am] = ra.w;
        *(float4*)&Bs[brow][bch] = rb;
        __syncthreads();
        if (k0 + 8 < E_) {
            ra = *(const float4*)(x + (m0 + am) * E_ + k0 + 8 + akp);
            rb = *(const float4*)(Bm + (k0 + 8 + brow) * HD_ + nb + bch);
        }
        #pragma unroll
        for (int kk = 0; kk < 8; kk++) {
            float4 a0 = *(const float4*)&As[kk][ty * 4];
            float4 a1 = *(const float4*)&As[kk][64 + ty * 4];
            float4 b0 = *(const float4*)&Bs[kk][tx * 4];
            float4 b1 = *(const float4*)&Bs[kk][64 + tx * 4];
            float a[8] = {a0.x,a0.y,a0.z,a0.w,a1.x,a1.y,a1.z,a1.w};
            float b[8] = {b0.x,b0.y,b0.z,b0.w,b1.x,b1.y,b1.z,b1.w};
            #pragma unroll
            for (int i = 0; i < 8; i++)
                #pragma unroll
                for (int j = 0; j < 8; j++) acc[i][j] += a[i] * b[j];
        }
        __syncthreads();
    }

    #pragma unroll
    for (int fi = 0; fi < 2; fi++)
        #pragma unroll
        for (int i = 0; i < 4; i++) {
            int m = m0 + fi * 64 + ty * 4 + i;
            int b = m >> 9, t = m & 511;
            #pragma unroll
            for (int fj = 0; fj < 2; fj++) {
                int nloc = nb + fj * 64 + tx * 4;
                int h = nloc >> 6, d = nloc & 63;
                float4 v = make_float4(acc[fi*4+i][fj*4+0], acc[fi*4+i][fj*4+1],
                                       acc[fi*4+i][fj*4+2], acc[fi*4+i][fj*4+3]);
                *(float4*)(C + (((b << 3) + h) * T_ + t) * D_ + d) = v;
            }
        }
}

// ---------------------------------------------------------------------------
// 2a) Causal logits GEMM: 128x64 tiles over lower triangle.  grid (20, 32)
//     256 thr, 8x4 micro, BK=16, prefetch.
// ---------------------------------------------------------------------------
#define L2STR 132
#define LBSTR 68
__global__ __launch_bounds__(256)
void logits_kernel()
{
    int l = blockIdx.x;              // 0..19
    int ti, tj;
    if (l < 2)       { ti = 0; tj = l; }
    else if (l < 6)  { ti = 1; tj = l - 2; }
    else if (l < 12) { ti = 2; tj = l - 6; }
    else             { ti = 3; tj = l - 12; }

    const int z  = blockIdx.y;          // r*16 + bh
    const int r  = z >> 4;
    const int bh = z & 15;
    const float* Qb = g_Q + bh * T_ * D_;
    const float* Kb = (r ? g_K1 : g_K0) + bh * T_ * D_;
    float* Lb = g_L + (size_t)z * T_ * T_;

    const int t0 = ti * 128, s0 = tj * 64;
    const int tid = threadIdx.x;
    const int tx = tid & 15, ty = tid >> 4;

    __shared__ float As[16][L2STR];   // [d][t] 128 wide
    __shared__ float Bs[16][LBSTR];   // [d][s] 64 wide

    const int am = tid >> 1, akp = (tid & 1) * 8;
    const int bm = tid >> 2, bkp = (tid & 3) * 4;

    float acc[8][4];
    #pragma unroll
    for (int i = 0; i < 8; i++)
        #pragma unroll
        for (int j = 0; j < 4; j++) acc[i][j] = 0.f;

    float4 ra0 = *(const float4*)(Qb + (t0 + am) * D_ + akp);
    float4 ra1 = *(const float4*)(Qb + (t0 + am) * D_ + akp + 4);
    float4 rb  = *(const float4*)(Kb + (s0 + bm) * D_ + bkp);

    for (int k0 = 0; k0 < D_; k0 += 16) {
        As[akp + 0][am] = ra0.x; As[akp + 1][am] = ra0.y;
        As[akp + 2][am] = ra0.z; As[akp + 3][am] = ra0.w;
        As[akp + 4][am] = ra1.x; As[akp + 5][am] = ra1.y;
        As[akp + 6][am] = ra1.z; As[akp + 7][am] = ra1.w;
        Bs[bkp + 0][bm] = rb.x;  Bs[bkp + 1][bm] = rb.y;
        Bs[bkp + 2][bm] = rb.z;  Bs[bkp + 3][bm] = rb.w;
        __syncthreads();
        if (k0 + 16 < D_) {
            ra0 = *(const float4*)(Qb + (t0 + am) * D_ + k0 + 16 + akp);
            ra1 = *(const float4*)(Qb + (t0 + am) * D_ + k0 + 16 + akp + 4);
            rb  = *(const float4*)(Kb + (s0 + bm) * D_ + k0 + 16 + bkp);
        }
        #pragma unroll
        for (int kk = 0; kk < 16; kk++) {
            float4 a0 = *(const float4*)&As[kk][ty * 8];
            float4 a1 = *(const float4*)&As[kk][ty * 8 + 4];
            float4 bv = *(const float4*)&Bs[kk][tx * 4];
            float a[8] = {a0.x,a0.y,a0.z,a0.w,a1.x,a1.y,a1.z,a1.w};
            float b[4] = {bv.x, bv.y, bv.z, bv.w};
            #pragma unroll
            for (int i = 0; i < 8; i++)
                #pragma unroll
                for (int j = 0; j < 4; j++) acc[i][j] += a[i] * b[j];
        }
        __syncthreads();
    }
    #pragma unroll
    for (int i = 0; i < 8; i++) {
        float4 v = make_float4(acc[i][0], acc[i][1], acc[i][2], acc[i][3]);
        *(float4*)(Lb + (t0 + ty * 8 + i) * T_ + s0 + tx * 4) = v;
    }
}

// ---------------------------------------------------------------------------
// 2b) Top-64 select.  grid (T, BH, 2), block 256.
// ---------------------------------------------------------------------------
__device__ __forceinline__ void cex(ull &v, int i, int j, int k) {
    ull o = __shfl_xor_sync(0xffffffffu, v, j);
    bool lower = ((i & j) == 0);
    bool desc  = ((i & k) == 0);
    bool keepMax = (lower == desc);
    bool gt = v > o;
    v = (keepMax == gt) ? v : o;
}
__device__ __forceinline__ void mstep(ull &v, int i, int j) {
    ull o = __shfl_xor_sync(0xffffffffu, v, j);
    bool keepMax = ((i & j) == 0);
    bool gt = v > o;
    v = (keepMax == gt) ? v : o;
}

__global__ __launch_bounds__(256)
void select_kernel()
{
    const int t  = blockIdx.x;
    const int bh = blockIdx.y;
    const int r  = blockIdx.z;
    const float* Lrow = g_L + ((size_t)(r * 16 + bh) * T_ + t) * T_;
    int* dst = (r == 0 ? g_idx0 : g_idx1) + (bh * T_ + t) * KK_;

    __shared__ ull keys[T_];

    const int tid  = threadIdx.x;
    const int lane = tid & 31;
    const int warp = tid >> 5;

    if (t < 63) {
        ull k = ~0ull;
        if (tid <= t) {
            unsigned u = __float_as_uint(Lrow[tid]);
            u ^= (u & 0x80000000u) ? 0xFFFFFFFFu : 0x80000000u;
            k = ((ull)u << 32) | (unsigned)(~(unsigned)tid);
        }
        #pragma unroll
        for (int o = 16; o > 0; o >>= 1) {
            ull v = __shfl_xor_sync(0xffffffffu, k, o);
            k = v < k ? v : k;
        }
        if (lane == 0) keys[warp] = k;
        __syncthreads();
        if (tid < KK_) {
            ull m = keys[0];
            ull v1 = keys[1];
            m = v1 < m ? v1 : m;
            int weak = (int)(~(unsigned)(m & 0xffffffffull));
            dst[tid] = (tid <= t) ? tid : weak;
        }
        return;
    }

    keys[tid]       = 0ull;
    keys[tid + 256] = 0ull;
    __syncthreads();

    for (int s = tid; s <= t; s += 256) {
        unsigned u = __float_as_uint(Lrow[s]);
        u ^= (u & 0x80000000u) ? 0xFFFFFFFFu : 0x80000000u;
        keys[s] = ((ull)u << 32) | (unsigned)(~(unsigned)s);
    }
    __syncthreads();

    ull r0 = keys[warp * 64 + lane];
    ull r1 = keys[warp * 64 + 32 + lane];
    if (warp * 64 <= t) {
        #pragma unroll
        for (int k = 2; k <= 64; k <<= 1) {
            #pragma unroll
            for (int j = k >> 1; j > 0; j >>= 1) {
                if (j == 32) {
                    ull hi = r0 > r1 ? r0 : r1;
                    ull lo = r0 > r1 ? r1 : r0;
                    r0 = hi; r1 = lo;
                } else {
                    cex(r0, lane,      j, k);
                    cex(r1, lane + 32, j, k);
                }
            }
        }
    }

    #pragma unroll
    for (int s = 1; s <= 4; s <<= 1) {
        keys[warp * 64 + lane]      = r0;
        keys[warp * 64 + 32 + lane] = r1;
        __syncthreads();
        if ((warp & ~(2 * s - 1)) * 64 <= t) {
            int p = warp ^ s;
            ull o0 = keys[p * 64 + 63 - lane];
            ull o1 = keys[p * 64 + 31 - lane];
            r0 = r0 > o0 ? r0 : o0;
            r1 = r1 > o1 ? r1 : o1;
            if (s < 4) {
                ull hi = r0 > r1 ? r0 : r1;
                ull lo = r0 > r1 ? r1 : r0;
                r0 = hi; r1 = lo;
                #pragma unroll
                for (int j = 16; j > 0; j >>= 1) {
                    mstep(r0, lane,      j);
                    mstep(r1, lane + 32, j);
                }
            }
        }
        __syncthreads();
    }

    if (warp == 0) {
        dst[lane]      = (int)(~(unsigned)(r0 & 0xffffffffull));
        dst[lane + 32] = (int)(~(unsigned)(r1 & 0xffffffffull));
    }
}

// ---------------------------------------------------------------------------
// 3) Order-3 attention, bf16 TC + ldmatrix, register softmax, fused V0 epilogue.
//    256 thr, 5 blocks/SM.
// ---------------------------------------------------------------------------
#define PLW(r, dp) (((r) << 5) + ((dp) ^ (((r) & 7) << 2)))
#define ATT_SMEM (4 * 2048 * 4 + (64 + 128 + 128 + 256) * 4 + 2 * 64 * 4)

__device__ __forceinline__ unsigned pack_bf(float x, float y) {
    __nv_bfloat162 h = __floats2bfloat162_rn(x, y);
    return *(unsigned*)&h;
}
__device__ __forceinline__ void bsplit(float x, float y, unsigned &h, unsigned &l) {
    __nv_bfloat162 hh = __floats2bfloat162_rn(x, y);
    h = *(unsigned*)&hh;
    l = pack_bf(x - __bfloat162float(hh.x), y - __bfloat162float(hh.y));
}
__device__ __forceinline__ void bmma(float* c, const unsigned* a,
                                     unsigned b0, unsigned b1) {
    asm("mma.sync.aligned.m16n8k16.row.col.f32.bf16.bf16.f32 "
        "{%0,%1,%2,%3},{%4,%5,%6,%7},{%8,%9},{%0,%1,%2,%3};"
        : "+f"(c[0]), "+f"(c[1]), "+f"(c[2]), "+f"(c[3])
        : "r"(a[0]), "r"(a[1]), "r"(a[2]), "r"(a[3]), "r"(b0), "r"(b1));
}
__device__ __forceinline__ void ldsm4(unsigned addr, unsigned &r0, unsigned &r1,
                                      unsigned &r2, unsigned &r3) {
    asm volatile("ldmatrix.sync.aligned.m8n8.x4.shared.b16 {%0,%1,%2,%3}, [%4];"
        : "=r"(r0), "=r"(r1), "=r"(r2), "=r"(r3) : "r"(addr));
}
__device__ __forceinline__ void ldsm4t(unsigned addr, unsigned &r0, unsigned &r1,
                                       unsigned &r2, unsigned &r3) {
    asm volatile("ldmatrix.sync.aligned.m8n8.x4.trans.shared.b16 {%0,%1,%2,%3}, [%4];"
        : "=r"(r0), "=r"(r1), "=r"(r2), "=r"(r3) : "r"(addr));
}

__global__ __launch_bounds__(256, 5)
void attn_kernel()
{
    extern __shared__ float sm[];
    unsigned* PAh = (unsigned*)sm;            // P0 hi -> alpha hi
    unsigned* PAl = PAh + 2048;
    unsigned* PBh = PAl + 2048;               // K1 hi -> V1 hi
    unsigned* PBl = PBh + 2048;
    float* qs   = (float*)(PBl + 2048);       // 64: q
    float* pmax = qs + 64;                    // 128
    float* psum = pmax + 128;                 // 128
    float* part = psum + 128;                 // 256
    int*   si0  = (int*)(part + 256);
    int*   si1  = si0 + 64;

    const int t  = blockIdx.x;
    const int bh = blockIdx.y;
    const int tid = threadIdx.x;
    const int lane = tid & 31;
    const int warp = tid >> 5;
    const int gi = lane >> 2;
    const int ti = lane & 3;
    const int l7 = lane & 7;
    const int mi = lane >> 3;
    const int wm = (warp & 3) * 16;       // m rows
    const int wn = (warp >> 2) * 32;      // n half
    const int pw = warp ^ 4;              // partner warp

    const unsigned uPAh = (unsigned)__cvta_generic_to_shared(PAh);
    const unsigned uPAl = uPAh + 8192;
    const unsigned uPBh = uPAh + 16384;
    const unsigned uPBl = uPAh + 24576;

    const float* K0b = g_K0 + bh * T_ * D_;
    const float* K1b = g_K1 + bh * T_ * D_;
    const float* V0b = g_V0 + bh * T_ * D_;
    const float* V1b = g_V1 + bh * T_ * D_;

    if (tid < 64) {
        qs[tid]  = g_Q[(bh * T_ + t) * D_ + tid];
        si0[tid] = g_idx0[(bh * T_ + t) * KK_ + tid];
        si1[tid] = g_idx1[(bh * T_ + t) * KK_ + tid];
    }
    __syncthreads();

    // gather: P0 split -> PA planes; K1g split -> PB planes  ([row][dpair])
    #pragma unroll
    for (int it = 0; it < 4; it++) {
        int i4 = tid + it * 256;
        int j = i4 >> 4, c = (i4 & 15) << 2;
        float4 v0 = *(const float4*)(K0b + si0[j] * D_ + c);
        unsigned h0, l0, h1, l1;
        bsplit(qs[c+0]*v0.x, qs[c+1]*v0.y, h0, l0);
        bsplit(qs[c+2]*v0.z, qs[c+3]*v0.w, h1, l1);
        int off = PLW(j, c >> 1);
        *(uint2*)&PAh[off] = make_uint2(h0, h1);
        *(uint2*)&PAl[off] = make_uint2(l0, l1);
        float4 v1 = *(const float4*)(K1b + si1[j] * D_ + c);
        bsplit(v1.x, v1.y, h0, l0);
        bsplit(v1.z, v1.w, h1, l1);
        *(uint2*)&PBh[off] = make_uint2(h0, h1);
        *(uint2*)&PBl[off] = make_uint2(l0, l1);
    }
    __syncthreads();

    const int rA  = wm + ((mi & 1) << 3) + l7;
    const int rB1 = ((mi >> 1) << 3) + l7;
    const int rB2 = ((mi & 1) << 3) + l7;

    // mm1: logits[j][kidx] = sum_d P0[j][d] * K1g[kidx][d]
    float acc[4][4];
    #pragma unroll
    for (int n = 0; n < 4; n++)
        #pragma unroll
        for (int i = 0; i < 4; i++) acc[n][i] = 0.f;
    #pragma unroll
    for (int kc = 0; kc < 4; kc++) {
        unsigned ah[4], al[4], bhv[8], blv[8];
        unsigned offA = ((rA << 5) + (((2*kc + (mi >> 1)) ^ l7) << 2)) << 2;
        ldsm4(uPAh + offA, ah[0], ah[1], ah[2], ah[3]);
        ldsm4(uPAl + offA, al[0], al[1], al[2], al[3]);
        unsigned cB = ((2*kc + (mi & 1)) ^ l7) << 2;
        unsigned offB0 = (((wn      + rB1) << 5) + cB) << 2;
        unsigned offB1 = (((wn + 16 + rB1) << 5) + cB) << 2;
        ldsm4(uPBh + offB0, bhv[0], bhv[1], bhv[2], bhv[3]);
        ldsm4(uPBh + offB1, bhv[4], bhv[5], bhv[6], bhv[7]);
        ldsm4(uPBl + offB0, blv[0], blv[1], blv[2], blv[3]);
        ldsm4(uPBl + offB1, blv[4], blv[5], blv[6], blv[7]);
        #pragma unroll
        for (int nt = 0; nt < 4; nt++) {
            bmma(acc[nt], ah, bhv[2*nt], bhv[2*nt+1]);
            bmma(acc[nt], ah, blv[2*nt], blv[2*nt+1]);
            bmma(acc[nt], al, bhv[2*nt], bhv[2*nt+1]);
        }
    }
    #pragma unroll
    for (int n = 0; n < 4; n++)
        #pragma unroll
        for (int i = 0; i < 4; i++) acc[n][i] *= 0.125f;

    // register softmax
    float m0 = -1e30f, m1 = -1e30f;
    #pragma unroll
    for (int n = 0; n < 4; n++) {
        m0 = fmaxf(m0, fmaxf(acc[n][0], acc[n][1]));
        m1 = fmaxf(m1, fmaxf(acc[n][2], acc[n][3]));
    }
    m0 = fmaxf(m0, __shfl_xor_sync(0xffffffffu, m0, 1));
    m0 = fmaxf(m0, __shfl_xor_sync(0xffffffffu, m0, 2));
    m1 = fmaxf(m1, __shfl_xor_sync(0xffffffffu, m1, 1));
    m1 = fmaxf(m1, __shfl_xor_sync(0xffffffffu, m1, 2));
    if (ti == 0) {
        pmax[warp * 16 + gi]     = m0;
        pmax[warp * 16 + 8 + gi] = m1;
    }
    __syncthreads();    // B1

    m0 = fmaxf(m0, pmax[pw * 16 + gi]);
    m1 = fmaxf(m1, pmax[pw * 16 + 8 + gi]);
    float s0 = 0.f, s1 = 0.f;
    #pragma unroll
    for (int n = 0; n < 4; n++) {
        acc[n][0] = __expf(acc[n][0] - m0);
        acc[n][1] = __expf(acc[n][1] - m0);
        acc[n][2] = __expf(acc[n][2] - m1);
        acc[n][3] = __expf(acc[n][3] - m1);
        s0 += acc[n][0] + acc[n][1];
        s1 += acc[n][2] + acc[n][3];
    }
    s0 += __shfl_xor_sync(0xffffffffu, s0, 1);
    s0 += __shfl_xor_sync(0xffffffffu, s0, 2);
    s1 += __shfl_xor_sync(0xffffffffu, s1, 1);
    s1 += __shfl_xor_sync(0xffffffffu, s1, 2);
    if (ti == 0) {
        psum[warp * 16 + gi]     = s0;
        psum[warp * 16 + 8 + gi] = s1;
    }

    // split exp (registers) -> PA planes [row][kpair]
    {
        int cp = (wn >> 1) + ti;
        #pragma unroll
        for (int n = 0; n < 4; n++) {
            unsigned h, l;
            int o0 = PLW(wm + gi, cp + n * 4);
            bsplit(acc[n][0], acc[n][1], h, l);
            PAh[o0] = h; PAl[o0] = l;
            int o1 = PLW(wm + gi + 8, cp + n * 4);
            bsplit(acc[n][2], acc[n][3], h, l);
            PAh[o1] = h; PAl[o1] = l;
        }
    }
    // V1 gather -> PB planes [k][dpair]
    #pragma unroll
    for (int it = 0; it < 4; it++) {
        int i4 = tid + it * 256;
        int k = i4 >> 4, c = (i4 & 15) << 2;
        float4 v = *(const float4*)(V1b + si1[k] * D_ + c);
        unsigned h0, l0, h1, l1;
        bsplit(v.x, v.y, h0, l0);
        bsplit(v.z, v.w, h1, l1);
        int off = PLW(k, c >> 1);
        *(uint2*)&PBh[off] = make_uint2(h0, h1);
        *(uint2*)&PBl[off] = make_uint2(l0, l1);
    }
    __syncthreads();    // B2

    const float inv0 = __frcp_rn(s0 + psum[pw * 16 + gi]);
    const float inv1 = __frcp_rn(s1 + psum[pw * 16 + 8 + gi]);

    // mm2: W[j][d] = inv[j] * sum_k exp[j][k] * V1g[k][d]
    #pragma unroll
    for (int n = 0; n < 4; n++)
        #pragma unroll
        for (int i = 0; i < 4; i++) acc[n][i] = 0.f;
    #pragma unroll
    for (int kc = 0; kc < 4; kc++) {
        unsigned ah[4], al[4], bhv[8], blv[8];
        unsigned offA = ((rA << 5) + (((2*kc + (mi >> 1)) ^ l7) << 2)) << 2;
        ldsm4(uPAh + offA, ah[0], ah[1], ah[2], ah[3]);
        ldsm4(uPAl + offA, al[0], al[1], al[2], al[3]);
        int k0 = kc * 16;
        int cb2 = (wn >> 3) + (mi >> 1);
        unsigned offB0 = (((k0 + rB2) << 5) + ((cb2 ^ l7) << 2)) << 2;
        unsigned offB1 = (((k0 + rB2) << 5) + (((cb2 + 2) ^ l7) << 2)) << 2;
        ldsm4t(uPBh + offB0, bhv[0], bhv[1], bhv[2], bhv[3]);
        ldsm4t(uPBh + offB1, bhv[4], bhv[5], bhv[6], bhv[7]);
        ldsm4t(uPBl + offB0, blv[0], blv[1], blv[2], blv[3]);
        ldsm4t(uPBl + offB1, blv[4], blv[5], blv[6], blv[7]);
        #pragma unroll
        for (int nt = 0; nt < 4; nt++) {
            bmma(acc[nt], ah, bhv[2*nt], bhv[2*nt+1]);
            bmma(acc[nt], ah, blv[2*nt], blv[2*nt+1]);
            bmma(acc[nt], al, bhv[2*nt], bhv[2*nt+1]);
        }
    }

    // fused epilogue: out[c] = sum_j (acc*inv)[j][c] * V0g[j][c]
    {
        float p[8];
        int r0 = wm + gi;
        int s0i = si0[r0], s1i = si0[r0 + 8];
        #pragma unroll
        for (int nt = 0; nt < 4; nt++) {
            int c0 = wn + nt * 8 + 2 * ti;
            float2 va = *(const float2*)(V0b + s0i * D_ + c0);
            float2 vb = *(const float2*)(V0b + s1i * D_ + c0);
            p[2*nt]   = acc[nt][0] * inv0 * va.x + acc[nt][2] * inv1 * vb.x;
            p[2*nt+1] = acc[nt][1] * inv0 * va.y + acc[nt][3] * inv1 * vb.y;
        }
        #pragma unroll
        for (int o = 4; o <= 16; o <<= 1)
            #pragma unroll
            for (int i = 0; i < 8; i++)
                p[i] += __shfl_down_sync(0xffffffffu, p[i], o);
        if (gi == 0) {
            int base = (warp & 3) * 64 + wn + 2 * ti;
            #pragma unroll
            for (int nt = 0; nt < 4; nt++) {
                part[base + nt * 8]     = p[2*nt];
                part[base + nt * 8 + 1] = p[2*nt+1];
            }
        }
        __syncthreads();
        if (tid < 64) {
            float o = part[tid] + part[64 + tid] + part[128 + tid] + part[192 + tid];
            int b = bh >> 3, h = bh & 7;
            g_ctx[(b * T_ + t) * HD_ + h * D_ + tid] = o;
        }
    }
}

// ---------------------------------------------------------------------------
// 4) out = ctx @ Wo.  64x64 tile, split-K=2 (atomicAdd), grid (8,16,2).
// ---------------------------------------------------------------------------
#define OASTR 68
__global__ __launch_bounds__(256)
void out_kernel(const float* __restrict__ Wo, float* __restrict__ out)
{
    const int n0 = blockIdx.x * 64;
    const int m0 = blockIdx.y * 64;
    const int kbase = blockIdx.z * 256;
    const int tid = threadIdx.x;
    const int tx = tid & 15, ty = tid >> 4;

    __shared__ float As[16][OASTR];
    __shared__ float Bs[16][64];

    const int am = tid >> 2, akp = (tid & 3) * 4;
    const int brow = tid >> 4, bch = (tid & 15) * 4;

    float acc[4][4];
    #pragma unroll
    for (int i = 0; i < 4; i++)
        #pragma unroll
        for (int j = 0; j < 4; j++) acc[i][j] = 0.f;

    float4 ra = *(const float4*)(g_ctx + (m0 + am) * HD_ + kbase + akp);
    float4 rb = *(const float4*)(Wo + (kbase + brow) * E_ + n0 + bch);

    for (int k0 = kbase; k0 < kbase + 256; k0 += 16) {
        As[akp + 0][am] = ra.x; As[akp + 1][am] = ra.y;
        As[akp + 2][am] = ra.z; As[akp + 3][am] = ra.w;
        *(float4*)&Bs[brow][bch] = rb;
        __syncthreads();
        if (k0 + 16 < kbase + 256) {
            ra = *(const float4*)(g_ctx + (m0 + am) * HD_ + k0 + 16 + akp);
            rb = *(const float4*)(Wo + (k0 + 16 + brow) * E_ + n0 + bch);
        }
        #pragma unroll
        for (int kk = 0; kk < 16; kk++) {
            float4 av = *(const float4*)&As[kk][ty * 4];
            float4 bv = *(const float4*)&Bs[kk][tx * 4];
            float a[4] = {av.x, av.y, av.z, av.w};
            float b[4] = {bv.x, bv.y, bv.z, bv.w};
            #pragma unroll
            for (int i = 0; i < 4; i++)
                #pragma unroll
                for (int j = 0; j < 4; j++) acc[i][j] += a[i] * b[j];
        }
        __syncthreads();
    }
    #pragma unroll
    for (int i = 0; i < 4; i++) {
        float* row = out + (m0 + ty * 4 + i) * E_ + n0 + tx * 4;
        #pragma unroll
        for (int j = 0; j < 4; j++)
            atomicAdd(row + j, acc[i][j]);
    }
}

// ---------------------------------------------------------------------------
extern "C" void kernel_launch(void* const* d_in, const int* in_sizes, int n_in,
                              void* d_out, int out_size)
{
    const float* x  = (const float*)d_in[0];
    const float* Wq = (const float*)d_in[1];
    const float* Wk = (const float*)d_in[2];
    const float* Wv = (const float*)d_in[3];
    const float* Wo = (const float*)d_in[4];
    float* out = (float*)d_out;

    cudaFuncSetAttribute(attn_kernel,
                         cudaFuncAttributeMaxDynamicSharedMemorySize, ATT_SMEM);

    dim3 gProj(20, 8);
    proj_kernel<<<gProj, 256>>>(x, Wq, Wk, Wv);

    dim3 gLog(20, 32);
    logits_kernel<<<gLog, 256>>>();

    dim3 gSel(T_, BH_, 2);
    select_kernel<<<gSel, 256>>>();

    dim3 gAtt(T_, BH_);
    attn_kernel<<<gAtt, 256, ATT_SMEM>>>();

    int n4 = out_size / 4;
    zero_kernel<<<(n4 + 255) / 256, 256>>>(out, n4);

    dim3 gOut(E_ / 64, M_ / 64, 2);
    out_kernel<<<gOut, 256>>>(Wo, out);
}

// round 16
// speedup vs baseline: 1.0169x; 1.0169x over previous
#include <cuda_runtime.h>
#include <cuda_bf16.h>
#include <math.h>

// build-id: r15-recombination-v2 (R12 kernels + R13 logits; hash-breaking edit)

#define B_  2
#define T_  512
#define H_  8
#define D_  64
#define E_  512
#define HD_ 512
#define BH_ 16
#define KK_ 64
#define M_  1024

typedef unsigned long long ull;

// ---------------- scratch ----------------
__device__ float g_Q [BH_ * T_ * D_];
__device__ float g_K0[BH_ * T_ * D_];
__device__ float g_K1[BH_ * T_ * D_];
__device__ float g_V0[BH_ * T_ * D_];
__device__ float g_V1[BH_ * T_ * D_];
__device__ float g_ctx[M_ * HD_];
__device__ float g_L[2 * BH_ * T_ * T_];    // causal logits, [r*16+bh][t][s]
__device__ int   g_idx0[BH_ * T_ * KK_];
__device__ int   g_idx1[BH_ * T_ * KK_];

// ---------------------------------------------------------------------------
// 0) zero d_out (split-K accumulator init)
// ---------------------------------------------------------------------------
__global__ __launch_bounds__(256)
void zero_kernel(float* __restrict__ out, int nquads)
{
    int idx = blockIdx.x * blockDim.x + threadIdx.x;
    if (idx < nquads) ((float4*)out)[idx] = make_float4(0.f, 0.f, 0.f, 0.f);
}

// ---------------------------------------------------------------------------
// 1) Projections: 128x128 tile, 256 thr, 8x8 micro, BK=8, prefetch. grid(20,8)
// ---------------------------------------------------------------------------
#define ASTR 132
__global__ __launch_bounds__(256)
void proj_kernel(const float* __restrict__ x,
                 const float* __restrict__ Wq,
                 const float* __restrict__ Wk,
                 const float* __restrict__ Wv)
{
    const int bx = blockIdx.x;
    const int z  = bx >> 2;
    const int nb = (bx & 3) * 128;
    const int m0 = blockIdx.y * 128;

    const float* Bm = (z == 0) ? Wq
                    : (z <= 2) ? (Wk + (z - 1) * (E_ * HD_))
                               : (Wv + (z - 3) * (E_ * HD_));
    float* C = (z == 0) ? g_Q : (z == 1) ? g_K0 : (z == 2) ? g_K1
             : (z == 3) ? g_V0 : g_V1;

    const int tid = threadIdx.x;
    const int tx = tid & 15, ty = tid >> 4;

    __shared__ float As[8][ASTR];
    __shared__ float Bs[8][128];

    const int am = tid >> 1, akp = (tid & 1) * 4;
    const int brow = tid >> 5, bch = (tid & 31) * 4;

    float acc[8][8];
    #pragma unroll
    for (int i = 0; i < 8; i++)
        #pragma unroll
        for (int j = 0; j < 8; j++) acc[i][j] = 0.f;

    float4 ra = *(const float4*)(x + (m0 + am) * E_ + akp);
    float4 rb = *(const float4*)(Bm + brow * HD_ + nb + bch);

    for (int k0 = 0; k0 < E_; k0 += 8) {
        As[akp + 0][am] = ra.x; As[akp + 1][am] = ra.y;
        As[akp + 2][am] = ra.z; As[akp + 3][am] = ra.w;
        *(float4*)&Bs[brow][bch] = rb;
        __syncthreads();
        if (k0 + 8 < E_) {
            ra = *(const float4*)(x + (m0 + am) * E_ + k0 + 8 + akp);
            rb = *(const float4*)(Bm + (k0 + 8 + brow) * HD_ + nb + bch);
        }
        #pragma unroll
        for (int kk = 0; kk < 8; kk++) {
            float4 a0 = *(const float4*)&As[kk][ty * 4];
            float4 a1 = *(const float4*)&As[kk][64 + ty * 4];
            float4 b0 = *(const float4*)&Bs[kk][tx * 4];
            float4 b1 = *(const float4*)&Bs[kk][64 + tx * 4];
            float a[8] = {a0.x,a0.y,a0.z,a0.w,a1.x,a1.y,a1.z,a1.w};
            float b[8] = {b0.x,b0.y,b0.z,b0.w,b1.x,b1.y,b1.z,b1.w};
            #pragma unroll
            for (int i = 0; i < 8; i++)
                #pragma unroll
                for (int j = 0; j < 8; j++) acc[i][j] += a[i] * b[j];
        }
        __syncthreads();
    }

    #pragma unroll
    for (int fi = 0; fi < 2; fi++)
        #pragma unroll
        for (int i = 0; i < 4; i++) {
            int m = m0 + fi * 64 + ty * 4 + i;
            int b = m >> 9, t = m & 511;
            #pragma unroll
            for (int fj = 0; fj < 2; fj++) {
                int nloc = nb + fj * 64 + tx * 4;
                int h = nloc >> 6, d = nloc & 63;
                float4 v = make_float4(acc[fi*4+i][fj*4+0], acc[fi*4+i][fj*4+1],
                                       acc[fi*4+i][fj*4+2], acc[fi*4+i][fj*4+3]);
                *(float4*)(C + (((b << 3) + h) * T_ + t) * D_ + d) = v;
            }
        }
}

// ---------------------------------------------------------------------------
// 2a) Causal logits GEMM: 128x64 tiles over lower triangle.  grid (20, 32)
//     256 thr, 8x4 micro, BK=16, prefetch.
// ---------------------------------------------------------------------------
#define L2STR 132
#define LBSTR 68
__global__ __launch_bounds__(256)
void logits_kernel()
{
    int l = blockIdx.x;              // 0..19
    int ti, tj;
    if (l < 2)       { ti = 0; tj = l; }
    else if (l < 6)  { ti = 1; tj = l - 2; }
    else if (l < 12) { ti = 2; tj = l - 6; }
    else             { ti = 3; tj = l - 12; }

    const int z  = blockIdx.y;          // r*16 + bh
    const int r  = z >> 4;
    const int bh = z & 15;
    const float* Qb = g_Q + bh * T_ * D_;
    const float* Kb = (r ? g_K1 : g_K0) + bh * T_ * D_;
    float* Lb = g_L + (size_t)z * T_ * T_;

    const int t0 = ti * 128, s0 = tj * 64;
    const int tid = threadIdx.x;
    const int tx = tid & 15, ty = tid >> 4;

    __shared__ float As[16][L2STR];   // [d][t] 128 wide
    __shared__ float Bs[16][LBSTR];   // [d][s] 64 wide

    const int am = tid >> 1, akp = (tid & 1) * 8;
    const int bm = tid >> 2, bkp = (tid & 3) * 4;

    float acc[8][4];
    #pragma unroll
    for (int i = 0; i < 8; i++)
        #pragma unroll
        for (int j = 0; j < 4; j++) acc[i][j] = 0.f;

    float4 ra0 = *(const float4*)(Qb + (t0 + am) * D_ + akp);
    float4 ra1 = *(const float4*)(Qb + (t0 + am) * D_ + akp + 4);
    float4 rb  = *(const float4*)(Kb + (s0 + bm) * D_ + bkp);

    for (int k0 = 0; k0 < D_; k0 += 16) {
        As[akp + 0][am] = ra0.x; As[akp + 1][am] = ra0.y;
        As[akp + 2][am] = ra0.z; As[akp + 3][am] = ra0.w;
        As[akp + 4][am] = ra1.x; As[akp + 5][am] = ra1.y;
        As[akp + 6][am] = ra1.z; As[akp + 7][am] = ra1.w;
        Bs[bkp + 0][bm] = rb.x;  Bs[bkp + 1][bm] = rb.y;
        Bs[bkp + 2][bm] = rb.z;  Bs[bkp + 3][bm] = rb.w;
        __syncthreads();
        if (k0 + 16 < D_) {
            ra0 = *(const float4*)(Qb + (t0 + am) * D_ + k0 + 16 + akp);
            ra1 = *(const float4*)(Qb + (t0 + am) * D_ + k0 + 16 + akp + 4);
            rb  = *(const float4*)(Kb + (s0 + bm) * D_ + k0 + 16 + bkp);
        }
        #pragma unroll
        for (int kk = 0; kk < 16; kk++) {
            float4 a0 = *(const float4*)&As[kk][ty * 8];
            float4 a1 = *(const float4*)&As[kk][ty * 8 + 4];
            float4 bv = *(const float4*)&Bs[kk][tx * 4];
            float a[8] = {a0.x,a0.y,a0.z,a0.w,a1.x,a1.y,a1.z,a1.w};
            float b[4] = {bv.x, bv.y, bv.z, bv.w};
            #pragma unroll
            for (int i = 0; i < 8; i++)
                #pragma unroll
                for (int j = 0; j < 4; j++) acc[i][j] += a[i] * b[j];
        }
        __syncthreads();
    }
    #pragma unroll
    for (int i = 0; i < 8; i++) {
        float4 v = make_float4(acc[i][0], acc[i][1], acc[i][2], acc[i][3]);
        *(float4*)(Lb + (t0 + ty * 8 + i) * T_ + s0 + tx * 4) = v;
    }
}

// ---------------------------------------------------------------------------
// 2b) Top-64 select.  grid (T, BH, 2), block 256.
// ---------------------------------------------------------------------------
__device__ __forceinline__ void cex(ull &v, int i, int j, int k) {
    ull o = __shfl_xor_sync(0xffffffffu, v, j);
    bool lower = ((i & j) == 0);
    bool desc  = ((i & k) == 0);
    bool keepMax = (lower == desc);
    bool gt = v > o;
    v = (keepMax == gt) ? v : o;
}
__device__ __forceinline__ void mstep(ull &v, int i, int j) {
    ull o = __shfl_xor_sync(0xffffffffu, v, j);
    bool keepMax = ((i & j) == 0);
    bool gt = v > o;
    v = (keepMax == gt) ? v : o;
}

__global__ __launch_bounds__(256)
void select_kernel()
{
    const int t  = blockIdx.x;
    const int bh = blockIdx.y;
    const int r  = blockIdx.z;
    const float* Lrow = g_L + ((size_t)(r * 16 + bh) * T_ + t) * T_;
    int* dst = (r == 0 ? g_idx0 : g_idx1) + (bh * T_ + t) * KK_;

    __shared__ ull keys[T_];

    const int tid  = threadIdx.x;
    const int lane = tid & 31;
    const int warp = tid >> 5;

    if (t < 63) {
        ull k = ~0ull;
        if (tid <= t) {
            unsigned u = __float_as_uint(Lrow[tid]);
            u ^= (u & 0x80000000u) ? 0xFFFFFFFFu : 0x80000000u;
            k = ((ull)u << 32) | (unsigned)(~(unsigned)tid);
        }
        #pragma unroll
        for (int o = 16; o > 0; o >>= 1) {
            ull v = __shfl_xor_sync(0xffffffffu, k, o);
            k = v < k ? v : k;
        }
        if (lane == 0) keys[warp] = k;
        __syncthreads();
        if (tid < KK_) {
            ull m = keys[0];
            ull v1 = keys[1];
            m = v1 < m ? v1 : m;
            int weak = (int)(~(unsigned)(m & 0xffffffffull));
            dst[tid] = (tid <= t) ? tid : weak;
        }
        return;
    }

    keys[tid]       = 0ull;
    keys[tid + 256] = 0ull;
    __syncthreads();

    for (int s = tid; s <= t; s += 256) {
        unsigned u = __float_as_uint(Lrow[s]);
        u ^= (u & 0x80000000u) ? 0xFFFFFFFFu : 0x80000000u;
        keys[s] = ((ull)u << 32) | (unsigned)(~(unsigned)s);
    }
    __syncthreads();

    ull r0 = keys[warp * 64 + lane];
    ull r1 = keys[warp * 64 + 32 + lane];
    if (warp * 64 <= t) {
        #pragma unroll
        for (int k = 2; k <= 64; k <<= 1) {
            #pragma unroll
            for (int j = k >> 1; j > 0; j >>= 1) {
                if (j == 32) {
                    ull hi = r0 > r1 ? r0 : r1;
                    ull lo = r0 > r1 ? r1 : r0;
                    r0 = hi; r1 = lo;
                } else {
                    cex(r0, lane,      j, k);
                    cex(r1, lane + 32, j, k);
                }
            }
        }
    }

    #pragma unroll
    for (int s = 1; s <= 4; s <<= 1) {
        keys[warp * 64 + lane]      = r0;
        keys[warp * 64 + 32 + lane] = r1;
        __syncthreads();
        if ((warp & ~(2 * s - 1)) * 64 <= t) {
            int p = warp ^ s;
            ull o0 = keys[p * 64 + 63 - lane];
            ull o1 = keys[p * 64 + 31 - lane];
            r0 = r0 > o0 ? r0 : o0;
            r1 = r1 > o1 ? r1 : o1;
            if (s < 4) {
                ull hi = r0 > r1 ? r0 : r1;
                ull lo = r0 > r1 ? r1 : r0;
                r0 = hi; r1 = lo;
                #pragma unroll
                for (int j = 16; j > 0; j >>= 1) {
                    mstep(r0, lane,      j);
                    mstep(r1, lane + 32, j);
                }
            }
        }
        __syncthreads();
    }

    if (warp == 0) {
        dst[lane]      = (int)(~(unsigned)(r0 & 0xffffffffull));
        dst[lane + 32] = (int)(~(unsigned)(r1 & 0xffffffffull));
    }
}

// ---------------------------------------------------------------------------
// 3) Order-3 attention, bf16 TC + ldmatrix, register softmax (R12 epilogue).
//    256 thr, 5 blocks/SM.
// ---------------------------------------------------------------------------
#define PLW(r, dp) (((r) << 5) + ((dp) ^ (((r) & 7) << 2)))
#define WIDX(row, pair) (((row) << 6) + (((pair) ^ (((row) & 7) << 2)) << 1))
#define ATT_SMEM (4 * 2048 * 4 + (64 + 128 + 128 + 256) * 4 + 2 * 64 * 4)

__device__ __forceinline__ unsigned pack_bf(float x, float y) {
    __nv_bfloat162 h = __floats2bfloat162_rn(x, y);
    return *(unsigned*)&h;
}
__device__ __forceinline__ void bsplit(float x, float y, unsigned &h, unsigned &l) {
    __nv_bfloat162 hh = __floats2bfloat162_rn(x, y);
    h = *(unsigned*)&hh;
    l = pack_bf(x - __bfloat162float(hh.x), y - __bfloat162float(hh.y));
}
__device__ __forceinline__ void bmma(float* c, const unsigned* a,
                                     unsigned b0, unsigned b1) {
    asm("mma.sync.aligned.m16n8k16.row.col.f32.bf16.bf16.f32 "
        "{%0,%1,%2,%3},{%4,%5,%6,%7},{%8,%9},{%0,%1,%2,%3};"
        : "+f"(c[0]), "+f"(c[1]), "+f"(c[2]), "+f"(c[3])
        : "r"(a[0]), "r"(a[1]), "r"(a[2]), "r"(a[3]), "r"(b0), "r"(b1));
}
__device__ __forceinline__ void ldsm4(unsigned addr, unsigned &r0, unsigned &r1,
                                      unsigned &r2, unsigned &r3) {
    asm volatile("ldmatrix.sync.aligned.m8n8.x4.shared.b16 {%0,%1,%2,%3}, [%4];"
        : "=r"(r0), "=r"(r1), "=r"(r2), "=r"(r3) : "r"(addr));
}
__device__ __forceinline__ void ldsm4t(unsigned addr, unsigned &r0, unsigned &r1,
                                       unsigned &r2, unsigned &r3) {
    asm volatile("ldmatrix.sync.aligned.m8n8.x4.trans.shared.b16 {%0,%1,%2,%3}, [%4];"
        : "=r"(r0), "=r"(r1), "=r"(r2), "=r"(r3) : "r"(addr));
}

__global__ __launch_bounds__(256, 5)
void attn_kernel()
{
    extern __shared__ float sm[];
    unsigned* PAh = (unsigned*)sm;            // P0 hi -> alpha hi -> W(fp32)
    unsigned* PAl = PAh + 2048;
    unsigned* PBh = PAl + 2048;               // K1 hi -> V1 hi
    unsigned* PBl = PBh + 2048;
    float* qs   = (float*)(PBl + 2048);       // 64: q
    float* pmax = qs + 64;                    // 128
    float* psum = pmax + 128;                 // 128
    float* part = psum + 128;                 // 256
    int*   si0  = (int*)(part + 256);
    int*   si1  = si0 + 64;

    const int t  = blockIdx.x;
    const int bh = blockIdx.y;
    const int tid = threadIdx.x;
    const int lane = tid & 31;
    const int warp = tid >> 5;
    const int gi = lane >> 2;
    const int ti = lane & 3;
    const int l7 = lane & 7;
    const int mi = lane >> 3;
    const int wm = (warp & 3) * 16;       // m rows
    const int wn = (warp >> 2) * 32;      // n half
    const int pw = warp ^ 4;              // partner warp

    const unsigned uPAh = (unsigned)__cvta_generic_to_shared(PAh);
    const unsigned uPAl = uPAh + 8192;
    const unsigned uPBh = uPAh + 16384;
    const unsigned uPBl = uPAh + 24576;

    const float* K0b = g_K0 + bh * T_ * D_;
    const float* K1b = g_K1 + bh * T_ * D_;
    const float* V0b = g_V0 + bh * T_ * D_;
    const float* V1b = g_V1 + bh * T_ * D_;

    if (tid < 64) {
        qs[tid]  = g_Q[(bh * T_ + t) * D_ + tid];
        si0[tid] = g_idx0[(bh * T_ + t) * KK_ + tid];
        si1[tid] = g_idx1[(bh * T_ + t) * KK_ + tid];
    }
    __syncthreads();

    // gather: P0 split -> PA planes; K1g split -> PB planes  ([row][dpair])
    #pragma unroll
    for (int it = 0; it < 4; it++) {
        int i4 = tid + it * 256;
        int j = i4 >> 4, c = (i4 & 15) << 2;
        float4 v0 = *(const float4*)(K0b + si0[j] * D_ + c);
        unsigned h0, l0, h1, l1;
        bsplit(qs[c+0]*v0.x, qs[c+1]*v0.y, h0, l0);
        bsplit(qs[c+2]*v0.z, qs[c+3]*v0.w, h1, l1);
        int off = PLW(j, c >> 1);
        *(uint2*)&PAh[off] = make_uint2(h0, h1);
        *(uint2*)&PAl[off] = make_uint2(l0, l1);
        float4 v1 = *(const float4*)(K1b + si1[j] * D_ + c);
        bsplit(v1.x, v1.y, h0, l0);
        bsplit(v1.z, v1.w, h1, l1);
        *(uint2*)&PBh[off] = make_uint2(h0, h1);
        *(uint2*)&PBl[off] = make_uint2(l0, l1);
    }
    __syncthreads();

    // fragment lane geometry (row&7 == l7 for every matrix row below)
    const int rA  = wm + ((mi & 1) << 3) + l7;
    const int rB1 = ((mi >> 1) << 3) + l7;
    const int rB2 = ((mi & 1) << 3) + l7;

    // mm1: logits[j][kidx] = sum_d P0[j][d] * K1g[kidx][d]
    float acc[4][4];
    #pragma unroll
    for (int n = 0; n < 4; n++)
        #pragma unroll
        for (int i = 0; i < 4; i++) acc[n][i] = 0.f;
    #pragma unroll
    for (int kc = 0; kc < 4; kc++) {
        unsigned ah[4], al[4], bhv[8], blv[8];
        unsigned offA = ((rA << 5) + (((2*kc + (mi >> 1)) ^ l7) << 2)) << 2;
        ldsm4(uPAh + offA, ah[0], ah[1], ah[2], ah[3]);
        ldsm4(uPAl + offA, al[0], al[1], al[2], al[3]);
        unsigned cB = ((2*kc + (mi & 1)) ^ l7) << 2;
        unsigned offB0 = (((wn      + rB1) << 5) + cB) << 2;
        unsigned offB1 = (((wn + 16 + rB1) << 5) + cB) << 2;
        ldsm4(uPBh + offB0, bhv[0], bhv[1], bhv[2], bhv[3]);
        ldsm4(uPBh + offB1, bhv[4], bhv[5], bhv[6], bhv[7]);
        ldsm4(uPBl + offB0, blv[0], blv[1], blv[2], blv[3]);
        ldsm4(uPBl + offB1, blv[4], blv[5], blv[6], blv[7]);
        #pragma unroll
        for (int nt = 0; nt < 4; nt++) {
            bmma(acc[nt], ah, bhv[2*nt], bhv[2*nt+1]);
            bmma(acc[nt], ah, blv[2*nt], blv[2*nt+1]);
            bmma(acc[nt], al, bhv[2*nt], bhv[2*nt+1]);
        }
    }
    #pragma unroll
    for (int n = 0; n < 4; n++)
        #pragma unroll
        for (int i = 0; i < 4; i++) acc[n][i] *= 0.125f;

    // register softmax
    float m0 = -1e30f, m1 = -1e30f;
    #pragma unroll
    for (int n = 0; n < 4; n++) {
        m0 = fmaxf(m0, fmaxf(acc[n][0], acc[n][1]));
        m1 = fmaxf(m1, fmaxf(acc[n][2], acc[n][3]));
    }
    m0 = fmaxf(m0, __shfl_xor_sync(0xffffffffu, m0, 1));
    m0 = fmaxf(m0, __shfl_xor_sync(0xffffffffu, m0, 2));
    m1 = fmaxf(m1, __shfl_xor_sync(0xffffffffu, m1, 1));
    m1 = fmaxf(m1, __shfl_xor_sync(0xffffffffu, m1, 2));
    if (ti == 0) {
        pmax[warp * 16 + gi]     = m0;
        pmax[warp * 16 + 8 + gi] = m1;
    }
    __syncthreads();    // B1

    m0 = fmaxf(m0, pmax[pw * 16 + gi]);
    m1 = fmaxf(m1, pmax[pw * 16 + 8 + gi]);
    float s0 = 0.f, s1 = 0.f;
    #pragma unroll
    for (int n = 0; n < 4; n++) {
        acc[n][0] = __expf(acc[n][0] - m0);
        acc[n][1] = __expf(acc[n][1] - m0);
        acc[n][2] = __expf(acc[n][2] - m1);
        acc[n][3] = __expf(acc[n][3] - m1);
        s0 += acc[n][0] + acc[n][1];
        s1 += acc[n][2] + acc[n][3];
    }
    s0 += __shfl_xor_sync(0xffffffffu, s0, 1);
    s0 += __shfl_xor_sync(0xffffffffu, s0, 2);
    s1 += __shfl_xor_sync(0xffffffffu, s1, 1);
    s1 += __shfl_xor_sync(0xffffffffu, s1, 2);
    if (ti == 0) {
        psum[warp * 16 + gi]     = s0;
        psum[warp * 16 + 8 + gi] = s1;
    }

    // split exp (registers) -> PA planes [row][kpair]
    {
        int cp = (wn >> 1) + ti;
        #pragma unroll
        for (int n = 0; n < 4; n++) {
            unsigned h, l;
            int o0 = PLW(wm + gi, cp + n * 4);
            bsplit(acc[n][0], acc[n][1], h, l);
            PAh[o0] = h; PAl[o0] = l;
            int o1 = PLW(wm + gi + 8, cp + n * 4);
            bsplit(acc[n][2], acc[n][3], h, l);
            PAh[o1] = h; PAl[o1] = l;
        }
    }
    // V1 gather -> PB planes [k][dpair]
    #pragma unroll
    for (int it = 0; it < 4; it++) {
        int i4 = tid + it * 256;
        int k = i4 >> 4, c = (i4 & 15) << 2;
        float4 v = *(const float4*)(V1b + si1[k] * D_ + c);
        unsigned h0, l0, h1, l1;
        bsplit(v.x, v.y, h0, l0);
        bsplit(v.z, v.w, h1, l1);
        int off = PLW(k, c >> 1);
        *(uint2*)&PBh[off] = make_uint2(h0, h1);
        *(uint2*)&PBl[off] = make_uint2(l0, l1);
    }
    __syncthreads();    // B2

    const float inv0 = __frcp_rn(s0 + psum[pw * 16 + gi]);
    const float inv1 = __frcp_rn(s1 + psum[pw * 16 + 8 + gi]);

    // mm2: W[j][d] = inv[j] * sum_k exp[j][k] * V1g[k][d]
    #pragma unroll
    for (int n = 0; n < 4; n++)
        #pragma unroll
        for (int i = 0; i < 4; i++) acc[n][i] = 0.f;
    #pragma unroll
    for (int kc = 0; kc < 4; kc++) {
        unsigned ah[4], al[4], bhv[8], blv[8];
        unsigned offA = ((rA << 5) + (((2*kc + (mi >> 1)) ^ l7) << 2)) << 2;
        ldsm4(uPAh + offA, ah[0], ah[1], ah[2], ah[3]);
        ldsm4(uPAl + offA, al[0], al[1], al[2], al[3]);
        int k0 = kc * 16;
        int cb2 = (wn >> 3) + (mi >> 1);
        unsigned offB0 = (((k0 + rB2) << 5) + ((cb2 ^ l7) << 2)) << 2;
        unsigned offB1 = (((k0 + rB2) << 5) + (((cb2 + 2) ^ l7) << 2)) << 2;
        ldsm4t(uPBh + offB0, bhv[0], bhv[1], bhv[2], bhv[3]);
        ldsm4t(uPBh + offB1, bhv[4], bhv[5], bhv[6], bhv[7]);
        ldsm4t(uPBl + offB0, blv[0], blv[1], blv[2], blv[3]);
        ldsm4t(uPBl + offB1, blv[4], blv[5], blv[6], blv[7]);
        #pragma unroll
        for (int nt = 0; nt < 4; nt++) {
            bmma(acc[nt], ah, bhv[2*nt], bhv[2*nt+1]);
            bmma(acc[nt], ah, blv[2*nt], blv[2*nt+1]);
            bmma(acc[nt], al, bhv[2*nt], bhv[2*nt+1]);
        }
    }
    __syncthreads();    // B3: all mm2 reads of PA done

    // W (fp32, swizzled pairs) -> PA region
    float* Wb = (float*)PAh;
    #pragma unroll
    for (int nt = 0; nt < 4; nt++) {
        int pr = (wn >> 1) + nt * 4 + ti;
        *(float2*)&Wb[WIDX(wm + gi, pr)] =
            make_float2(acc[nt][0] * inv0, acc[nt][1] * inv0);
        *(float2*)&Wb[WIDX(wm + gi + 8, pr)] =
            make_float2(acc[nt][2] * inv1, acc[nt][3] * inv1);
    }
    __syncthreads();    // B4

    // out[d] = sum_j W[j][d] * V0g[j][d]
    {
        int d  = tid & 63;
        int jg = tid >> 6;             // 0..3
        int dp = d >> 1, db = d & 1;
        float s = 0.f;
        #pragma unroll
        for (int jj = 0; jj < 16; jj++) {
            int j = jg * 16 + jj;
            s += Wb[WIDX(j, dp) + db] * V0b[si0[j] * D_ + d];
        }
        part[jg * 64 + d] = s;
        __syncthreads();
        if (tid < 64) {
            float o = part[tid] + part[64 + tid] + part[128 + tid] + part[192 + tid];
            int b = bh >> 3, h = bh & 7;
            g_ctx[(b * T_ + t) * HD_ + h * D_ + tid] = o;
        }
    }
}

// ---------------------------------------------------------------------------
// 4) out = ctx @ Wo.  64x64 tile, split-K=2 (atomicAdd), grid (8,16,2).
// ---------------------------------------------------------------------------
#define OASTR 68
__global__ __launch_bounds__(256)
void out_kernel(const float* __restrict__ Wo, float* __restrict__ out)
{
    const int n0 = blockIdx.x * 64;
    const int m0 = blockIdx.y * 64;
    const int kbase = blockIdx.z * 256;
    const int tid = threadIdx.x;
    const int tx = tid & 15, ty = tid >> 4;

    __shared__ float As[16][OASTR];
    __shared__ float Bs[16][64];

    const int am = tid >> 2, akp = (tid & 3) * 4;
    const int brow = tid >> 4, bch = (tid & 15) * 4;

    float acc[4][4];
    #pragma unroll
    for (int i = 0; i < 4; i++)
        #pragma unroll
        for (int j = 0; j < 4; j++) acc[i][j] = 0.f;

    float4 ra = *(const float4*)(g_ctx + (m0 + am) * HD_ + kbase + akp);
    float4 rb = *(const float4*)(Wo + (kbase + brow) * E_ + n0 + bch);

    for (int k0 = kbase; k0 < kbase + 256; k0 += 16) {
        As[akp + 0][am] = ra.x; As[akp + 1][am] = ra.y;
        As[akp + 2][am] = ra.z; As[akp + 3][am] = ra.w;
        *(float4*)&Bs[brow][bch] = rb;
        __syncthreads();
        if (k0 + 16 < kbase + 256) {
            ra = *(const float4*)(g_ctx + (m0 + am) * HD_ + k0 + 16 + akp);
            rb = *(const float4*)(Wo + (k0 + 16 + brow) * E_ + n0 + bch);
        }
        #pragma unroll
        for (int kk = 0; kk < 16; kk++) {
            float4 av = *(const float4*)&As[kk][ty * 4];
            float4 bv = *(const float4*)&Bs[kk][tx * 4];
            float a[4] = {av.x, av.y, av.z, av.w};
            float b[4] = {bv.x, bv.y, bv.z, bv.w};
            #pragma unroll
            for (int i = 0; i < 4; i++)
                #pragma unroll
                for (int j = 0; j < 4; j++) acc[i][j] += a[i] * b[j];
        }
        __syncthreads();
    }
    #pragma unroll
    for (int i = 0; i < 4; i++) {
        float* row = out + (m0 + ty * 4 + i) * E_ + n0 + tx * 4;
        #pragma unroll
        for (int j = 0; j < 4; j++)
            atomicAdd(row + j, acc[i][j]);
    }
}

// ---------------------------------------------------------------------------
extern "C" void kernel_launch(void* const* d_in, const int* in_sizes, int n_in,
                              void* d_out, int out_size)
{
    const float* x  = (const float*)d_in[0];
    const float* Wq = (const float*)d_in[1];
    const float* Wk = (const float*)d_in[2];
    const float* Wv = (const float*)d_in[3];
    const float* Wo = (const float*)d_in[4];
    float* out = (float*)d_out;

    cudaFuncSetAttribute(attn_kernel,
                         cudaFuncAttributeMaxDynamicSharedMemorySize, ATT_SMEM);

    dim3 gProj(20, 8);
    proj_kernel<<<gProj, 256>>>(x, Wq, Wk, Wv);

    dim3 gLog(20, 32);
    logits_kernel<<<gLog, 256>>>();

    dim3 gSel(T_, BH_, 2);
    select_kernel<<<gSel, 256>>>();

    dim3 gAtt(T_, BH_);
    attn_kernel<<<gAtt, 256, ATT_SMEM>>>();

    int nquads = out_size / 4;
    zero_kernel<<<(nquads + 255) / 256, 256>>>(out, nquads);

    dim3 gOut(E_ / 64, M_ / 64, 2);
    out_kernel<<<gOut, 256>>>(Wo, out);
}

// round 17
// speedup vs baseline: 1.0382x; 1.0209x over previous
#include <cuda_runtime.h>
#include <cuda_bf16.h>
#include <math.h>

// build-id: r17-proj-retile (128x64 proj tiles, 320 blocks; rest == r16)

#define B_  2
#define T_  512
#define H_  8
#define D_  64
#define E_  512
#define HD_ 512
#define BH_ 16
#define KK_ 64
#define M_  1024

typedef unsigned long long ull;

// ---------------- scratch ----------------
__device__ float g_Q [BH_ * T_ * D_];
__device__ float g_K0[BH_ * T_ * D_];
__device__ float g_K1[BH_ * T_ * D_];
__device__ float g_V0[BH_ * T_ * D_];
__device__ float g_V1[BH_ * T_ * D_];
__device__ float g_ctx[M_ * HD_];
__device__ float g_L[2 * BH_ * T_ * T_];    // causal logits, [r*16+bh][t][s]
__device__ int   g_idx0[BH_ * T_ * KK_];
__device__ int   g_idx1[BH_ * T_ * KK_];

// ---------------------------------------------------------------------------
// 0) zero d_out (split-K accumulator init)
// ---------------------------------------------------------------------------
__global__ __launch_bounds__(256)
void zero_kernel(float* __restrict__ out, int nquads)
{
    int idx = blockIdx.x * blockDim.x + threadIdx.x;
    if (idx < nquads) ((float4*)out)[idx] = make_float4(0.f, 0.f, 0.f, 0.f);
}

// ---------------------------------------------------------------------------
// 1) Projections: 128x64 tile, 256 thr, 8x4 micro, BK=16, prefetch.
//    grid (40, 8) = 320 blocks (balanced waves on 148 SMs).
// ---------------------------------------------------------------------------
#define PASTR 132
#define PBSTR 68
__global__ __launch_bounds__(256)
void proj_kernel(const float* __restrict__ x,
                 const float* __restrict__ Wq,
                 const float* __restrict__ Wk,
                 const float* __restrict__ Wv)
{
    const int bx = blockIdx.x;           // 0..39 over concatenated N=2560
    const int z  = bx >> 3;              // which matrix (5)
    const int h  = bx & 7;               // 64-col tile within matrix = head
    const int nb = h * 64;
    const int m0 = blockIdx.y * 128;

    const float* Bm = (z == 0) ? Wq
                    : (z <= 2) ? (Wk + (z - 1) * (E_ * HD_))
                               : (Wv + (z - 3) * (E_ * HD_));
    float* C = (z == 0) ? g_Q : (z == 1) ? g_K0 : (z == 2) ? g_K1
             : (z == 3) ? g_V0 : g_V1;

    const int tid = threadIdx.x;
    const int tx = tid & 15, ty = tid >> 4;

    __shared__ float As[16][PASTR];   // [k][m] 128 wide (transposed)
    __shared__ float Bs[16][PBSTR];   // [k][n] 64 wide

    const int am = tid >> 1, akp = (tid & 1) * 8;      // A: 2 thr/row
    const int brow = tid >> 4, bch = (tid & 15) * 4;   // B: 16 rows x 64

    float acc[8][4];
    #pragma unroll
    for (int i = 0; i < 8; i++)
        #pragma unroll
        for (int j = 0; j < 4; j++) acc[i][j] = 0.f;

    float4 ra0 = *(const float4*)(x + (m0 + am) * E_ + akp);
    float4 ra1 = *(const float4*)(x + (m0 + am) * E_ + akp + 4);
    float4 rb  = *(const float4*)(Bm + brow * HD_ + nb + bch);

    for (int k0 = 0; k0 < E_; k0 += 16) {
        As[akp + 0][am] = ra0.x; As[akp + 1][am] = ra0.y;
        As[akp + 2][am] = ra0.z; As[akp + 3][am] = ra0.w;
        As[akp + 4][am] = ra1.x; As[akp + 5][am] = ra1.y;
        As[akp + 6][am] = ra1.z; As[akp + 7][am] = ra1.w;
        *(float4*)&Bs[brow][bch] = rb;
        __syncthreads();
        if (k0 + 16 < E_) {
            ra0 = *(const float4*)(x + (m0 + am) * E_ + k0 + 16 + akp);
            ra1 = *(const float4*)(x + (m0 + am) * E_ + k0 + 16 + akp + 4);
            rb  = *(const float4*)(Bm + (k0 + 16 + brow) * HD_ + nb + bch);
        }
        #pragma unroll
        for (int kk = 0; kk < 16; kk++) {
            float4 a0 = *(const float4*)&As[kk][ty * 8];
            float4 a1 = *(const float4*)&As[kk][ty * 8 + 4];
            float4 bv = *(const float4*)&Bs[kk][tx * 4];
            float a[8] = {a0.x,a0.y,a0.z,a0.w,a1.x,a1.y,a1.z,a1.w};
            float b[4] = {bv.x, bv.y, bv.z, bv.w};
            #pragma unroll
            for (int i = 0; i < 8; i++)
                #pragma unroll
                for (int j = 0; j < 4; j++) acc[i][j] += a[i] * b[j];
        }
        __syncthreads();
    }

    // head-split write: m -> (b, t), col = h*64 + tx*4 -> (h, d)
    #pragma unroll
    for (int i = 0; i < 8; i++) {
        int m = m0 + ty * 8 + i;
        int b = m >> 9, t = m & 511;
        float4 v = make_float4(acc[i][0], acc[i][1], acc[i][2], acc[i][3]);
        *(float4*)(C + (((b << 3) + h) * T_ + t) * D_ + tx * 4) = v;
    }
}

// ---------------------------------------------------------------------------
// 2a) Causal logits GEMM: 128x64 tiles over lower triangle.  grid (20, 32)
//     256 thr, 8x4 micro, BK=16, prefetch.
// ---------------------------------------------------------------------------
#define L2STR 132
#define LBSTR 68
__global__ __launch_bounds__(256)
void logits_kernel()
{
    int l = blockIdx.x;              // 0..19
    int ti, tj;
    if (l < 2)       { ti = 0; tj = l; }
    else if (l < 6)  { ti = 1; tj = l - 2; }
    else if (l < 12) { ti = 2; tj = l - 6; }
    else             { ti = 3; tj = l - 12; }

    const int z  = blockIdx.y;          // r*16 + bh
    const int r  = z >> 4;
    const int bh = z & 15;
    const float* Qb = g_Q + bh * T_ * D_;
    const float* Kb = (r ? g_K1 : g_K0) + bh * T_ * D_;
    float* Lb = g_L + (size_t)z * T_ * T_;

    const int t0 = ti * 128, s0 = tj * 64;
    const int tid = threadIdx.x;
    const int tx = tid & 15, ty = tid >> 4;

    __shared__ float As[16][L2STR];   // [d][t] 128 wide
    __shared__ float Bs[16][LBSTR];   // [d][s] 64 wide

    const int am = tid >> 1, akp = (tid & 1) * 8;
    const int bm = tid >> 2, bkp = (tid & 3) * 4;

    float acc[8][4];
    #pragma unroll
    for (int i = 0; i < 8; i++)
        #pragma unroll
        for (int j = 0; j < 4; j++) acc[i][j] = 0.f;

    float4 ra0 = *(const float4*)(Qb + (t0 + am) * D_ + akp);
    float4 ra1 = *(const float4*)(Qb + (t0 + am) * D_ + akp + 4);
    float4 rb  = *(const float4*)(Kb + (s0 + bm) * D_ + bkp);

    for (int k0 = 0; k0 < D_; k0 += 16) {
        As[akp + 0][am] = ra0.x; As[akp + 1][am] = ra0.y;
        As[akp + 2][am] = ra0.z; As[akp + 3][am] = ra0.w;
        As[akp + 4][am] = ra1.x; As[akp + 5][am] = ra1.y;
        As[akp + 6][am] = ra1.z; As[akp + 7][am] = ra1.w;
        Bs[bkp + 0][bm] = rb.x;  Bs[bkp + 1][bm] = rb.y;
        Bs[bkp + 2][bm] = rb.z;  Bs[bkp + 3][bm] = rb.w;
        __syncthreads();
        if (k0 + 16 < D_) {
            ra0 = *(const float4*)(Qb + (t0 + am) * D_ + k0 + 16 + akp);
            ra1 = *(const float4*)(Qb + (t0 + am) * D_ + k0 + 16 + akp + 4);
            rb  = *(const float4*)(Kb + (s0 + bm) * D_ + k0 + 16 + bkp);
        }
        #pragma unroll
        for (int kk = 0; kk < 16; kk++) {
            float4 a0 = *(const float4*)&As[kk][ty * 8];
            float4 a1 = *(const float4*)&As[kk][ty * 8 + 4];
            float4 bv = *(const float4*)&Bs[kk][tx * 4];
            float a[8] = {a0.x,a0.y,a0.z,a0.w,a1.x,a1.y,a1.z,a1.w};
            float b[4] = {bv.x, bv.y, bv.z, bv.w};
            #pragma unroll
            for (int i = 0; i < 8; i++)
                #pragma unroll
                for (int j = 0; j < 4; j++) acc[i][j] += a[i] * b[j];
        }
        __syncthreads();
    }
    #pragma unroll
    for (int i = 0; i < 8; i++) {
        float4 v = make_float4(acc[i][0], acc[i][1], acc[i][2], acc[i][3]);
        *(float4*)(Lb + (t0 + ty * 8 + i) * T_ + s0 + tx * 4) = v;
    }
}

// ---------------------------------------------------------------------------
// 2b) Top-64 select.  grid (T, BH, 2), block 256.
// ---------------------------------------------------------------------------
__device__ __forceinline__ void cex(ull &v, int i, int j, int k) {
    ull o = __shfl_xor_sync(0xffffffffu, v, j);
    bool lower = ((i & j) == 0);
    bool desc  = ((i & k) == 0);
    bool keepMax = (lower == desc);
    bool gt = v > o;
    v = (keepMax == gt) ? v : o;
}
__device__ __forceinline__ void mstep(ull &v, int i, int j) {
    ull o = __shfl_xor_sync(0xffffffffu, v, j);
    bool keepMax = ((i & j) == 0);
    bool gt = v > o;
    v = (keepMax == gt) ? v : o;
}

__global__ __launch_bounds__(256)
void select_kernel()
{
    const int t  = blockIdx.x;
    const int bh = blockIdx.y;
    const int r  = blockIdx.z;
    const float* Lrow = g_L + ((size_t)(r * 16 + bh) * T_ + t) * T_;
    int* dst = (r == 0 ? g_idx0 : g_idx1) + (bh * T_ + t) * KK_;

    __shared__ ull keys[T_];

    const int tid  = threadIdx.x;
    const int lane = tid & 31;
    const int warp = tid >> 5;

    if (t < 63) {
        ull k = ~0ull;
        if (tid <= t) {
            unsigned u = __float_as_uint(Lrow[tid]);
            u ^= (u & 0x80000000u) ? 0xFFFFFFFFu : 0x80000000u;
            k = ((ull)u << 32) | (unsigned)(~(unsigned)tid);
        }
        #pragma unroll
        for (int o = 16; o > 0; o >>= 1) {
            ull v = __shfl_xor_sync(0xffffffffu, k, o);
            k = v < k ? v : k;
        }
        if (lane == 0) keys[warp] = k;
        __syncthreads();
        if (tid < KK_) {
            ull m = keys[0];
            ull v1 = keys[1];
            m = v1 < m ? v1 : m;
            int weak = (int)(~(unsigned)(m & 0xffffffffull));
            dst[tid] = (tid <= t) ? tid : weak;
        }
        return;
    }

    keys[tid]       = 0ull;
    keys[tid + 256] = 0ull;
    __syncthreads();

    for (int s = tid; s <= t; s += 256) {
        unsigned u = __float_as_uint(Lrow[s]);
        u ^= (u & 0x80000000u) ? 0xFFFFFFFFu : 0x80000000u;
        keys[s] = ((ull)u << 32) | (unsigned)(~(unsigned)s);
    }
    __syncthreads();

    ull r0 = keys[warp * 64 + lane];
    ull r1 = keys[warp * 64 + 32 + lane];
    if (warp * 64 <= t) {
        #pragma unroll
        for (int k = 2; k <= 64; k <<= 1) {
            #pragma unroll
            for (int j = k >> 1; j > 0; j >>= 1) {
                if (j == 32) {
                    ull hi = r0 > r1 ? r0 : r1;
                    ull lo = r0 > r1 ? r1 : r0;
                    r0 = hi; r1 = lo;
                } else {
                    cex(r0, lane,      j, k);
                    cex(r1, lane + 32, j, k);
                }
            }
        }
    }

    #pragma unroll
    for (int s = 1; s <= 4; s <<= 1) {
        keys[warp * 64 + lane]      = r0;
        keys[warp * 64 + 32 + lane] = r1;
        __syncthreads();
        if ((warp & ~(2 * s - 1)) * 64 <= t) {
            int p = warp ^ s;
            ull o0 = keys[p * 64 + 63 - lane];
            ull o1 = keys[p * 64 + 31 - lane];
            r0 = r0 > o0 ? r0 : o0;
            r1 = r1 > o1 ? r1 : o1;
            if (s < 4) {
                ull hi = r0 > r1 ? r0 : r1;
                ull lo = r0 > r1 ? r1 : r0;
                r0 = hi; r1 = lo;
                #pragma unroll
                for (int j = 16; j > 0; j >>= 1) {
                    mstep(r0, lane,      j);
                    mstep(r1, lane + 32, j);
                }
            }
        }
        __syncthreads();
    }

    if (warp == 0) {
        dst[lane]      = (int)(~(unsigned)(r0 & 0xffffffffull));
        dst[lane + 32] = (int)(~(unsigned)(r1 & 0xffffffffull));
    }
}

// ---------------------------------------------------------------------------
// 3) Order-3 attention, bf16 TC + ldmatrix, register softmax (R12 epilogue).
//    256 thr, 5 blocks/SM.
// ---------------------------------------------------------------------------
#define PLW(r, dp) (((r) << 5) + ((dp) ^ (((r) & 7) << 2)))
#define WIDX(row, pair) (((row) << 6) + (((pair) ^ (((row) & 7) << 2)) << 1))
#define ATT_SMEM (4 * 2048 * 4 + (64 + 128 + 128 + 256) * 4 + 2 * 64 * 4)

__device__ __forceinline__ unsigned pack_bf(float x, float y) {
    __nv_bfloat162 h = __floats2bfloat162_rn(x, y);
    return *(unsigned*)&h;
}
__device__ __forceinline__ void bsplit(float x, float y, unsigned &h, unsigned &l) {
    __nv_bfloat162 hh = __floats2bfloat162_rn(x, y);
    h = *(unsigned*)&hh;
    l = pack_bf(x - __bfloat162float(hh.x), y - __bfloat162float(hh.y));
}
__device__ __forceinline__ void bmma(float* c, const unsigned* a,
                                     unsigned b0, unsigned b1) {
    asm("mma.sync.aligned.m16n8k16.row.col.f32.bf16.bf16.f32 "
        "{%0,%1,%2,%3},{%4,%5,%6,%7},{%8,%9},{%0,%1,%2,%3};"
        : "+f"(c[0]), "+f"(c[1]), "+f"(c[2]), "+f"(c[3])
        : "r"(a[0]), "r"(a[1]), "r"(a[2]), "r"(a[3]), "r"(b0), "r"(b1));
}
__device__ __forceinline__ void ldsm4(unsigned addr, unsigned &r0, unsigned &r1,
                                      unsigned &r2, unsigned &r3) {
    asm volatile("ldmatrix.sync.aligned.m8n8.x4.shared.b16 {%0,%1,%2,%3}, [%4];"
        : "=r"(r0), "=r"(r1), "=r"(r2), "=r"(r3) : "r"(addr));
}
__device__ __forceinline__ void ldsm4t(unsigned addr, unsigned &r0, unsigned &r1,
                                       unsigned &r2, unsigned &r3) {
    asm volatile("ldmatrix.sync.aligned.m8n8.x4.trans.shared.b16 {%0,%1,%2,%3}, [%4];"
        : "=r"(r0), "=r"(r1), "=r"(r2), "=r"(r3) : "r"(addr));
}

__global__ __launch_bounds__(256, 5)
void attn_kernel()
{
    extern __shared__ float sm[];
    unsigned* PAh = (unsigned*)sm;            // P0 hi -> alpha hi -> W(fp32)
    unsigned* PAl = PAh + 2048;
    unsigned* PBh = PAl + 2048;               // K1 hi -> V1 hi
    unsigned* PBl = PBh + 2048;
    float* qs   = (float*)(PBl + 2048);       // 64: q
    float* pmax = qs + 64;                    // 128
    float* psum = pmax + 128;                 // 128
    float* part = psum + 128;                 // 256
    int*   si0  = (int*)(part + 256);
    int*   si1  = si0 + 64;

    const int t  = blockIdx.x;
    const int bh = blockIdx.y;
    const int tid = threadIdx.x;
    const int lane = tid & 31;
    const int warp = tid >> 5;
    const int gi = lane >> 2;
    const int ti = lane & 3;
    const int l7 = lane & 7;
    const int mi = lane >> 3;
    const int wm = (warp & 3) * 16;       // m rows
    const int wn = (warp >> 2) * 32;      // n half
    const int pw = warp ^ 4;              // partner warp

    const unsigned uPAh = (unsigned)__cvta_generic_to_shared(PAh);
    const unsigned uPAl = uPAh + 8192;
    const unsigned uPBh = uPAh + 16384;
    const unsigned uPBl = uPAh + 24576;

    const float* K0b = g_K0 + bh * T_ * D_;
    const float* K1b = g_K1 + bh * T_ * D_;
    const float* V0b = g_V0 + bh * T_ * D_;
    const float* V1b = g_V1 + bh * T_ * D_;

    if (tid < 64) {
        qs[tid]  = g_Q[(bh * T_ + t) * D_ + tid];
        si0[tid] = g_idx0[(bh * T_ + t) * KK_ + tid];
        si1[tid] = g_idx1[(bh * T_ + t) * KK_ + tid];
    }
    __syncthreads();

    // gather: P0 split -> PA planes; K1g split -> PB planes  ([row][dpair])
    #pragma unroll
    for (int it = 0; it < 4; it++) {
        int i4 = tid + it * 256;
        int j = i4 >> 4, c = (i4 & 15) << 2;
        float4 v0 = *(const float4*)(K0b + si0[j] * D_ + c);
        unsigned h0, l0, h1, l1;
        bsplit(qs[c+0]*v0.x, qs[c+1]*v0.y, h0, l0);
        bsplit(qs[c+2]*v0.z, qs[c+3]*v0.w, h1, l1);
        int off = PLW(j, c >> 1);
        *(uint2*)&PAh[off] = make_uint2(h0, h1);
        *(uint2*)&PAl[off] = make_uint2(l0, l1);
        float4 v1 = *(const float4*)(K1b + si1[j] * D_ + c);
        bsplit(v1.x, v1.y, h0, l0);
        bsplit(v1.z, v1.w, h1, l1);
        *(uint2*)&PBh[off] = make_uint2(h0, h1);
        *(uint2*)&PBl[off] = make_uint2(l0, l1);
    }
    __syncthreads();

    // fragment lane geometry (row&7 == l7 for every matrix row below)
    const int rA  = wm + ((mi & 1) << 3) + l7;
    const int rB1 = ((mi >> 1) << 3) + l7;
    const int rB2 = ((mi & 1) << 3) + l7;

    // mm1: logits[j][kidx] = sum_d P0[j][d] * K1g[kidx][d]
    float acc[4][4];
    #pragma unroll
    for (int n = 0; n < 4; n++)
        #pragma unroll
        for (int i = 0; i < 4; i++) acc[n][i] = 0.f;
    #pragma unroll
    for (int kc = 0; kc < 4; kc++) {
        unsigned ah[4], al[4], bhv[8], blv[8];
        unsigned offA = ((rA << 5) + (((2*kc + (mi >> 1)) ^ l7) << 2)) << 2;
        ldsm4(uPAh + offA, ah[0], ah[1], ah[2], ah[3]);
        ldsm4(uPAl + offA, al[0], al[1], al[2], al[3]);
        unsigned cB = ((2*kc + (mi & 1)) ^ l7) << 2;
        unsigned offB0 = (((wn      + rB1) << 5) + cB) << 2;
        unsigned offB1 = (((wn + 16 + rB1) << 5) + cB) << 2;
        ldsm4(uPBh + offB0, bhv[0], bhv[1], bhv[2], bhv[3]);
        ldsm4(uPBh + offB1, bhv[4], bhv[5], bhv[6], bhv[7]);
        ldsm4(uPBl + offB0, blv[0], blv[1], blv[2], blv[3]);
        ldsm4(uPBl + offB1, blv[4], blv[5], blv[6], blv[7]);
        #pragma unroll
        for (int nt = 0; nt < 4; nt++) {
            bmma(acc[nt], ah, bhv[2*nt], bhv[2*nt+1]);
            bmma(acc[nt], ah, blv[2*nt], blv[2*nt+1]);
            bmma(acc[nt], al, bhv[2*nt], bhv[2*nt+1]);
        }
    }
    #pragma unroll
    for (int n = 0; n < 4; n++)
        #pragma unroll
        for (int i = 0; i < 4; i++) acc[n][i] *= 0.125f;

    // register softmax
    float m0 = -1e30f, m1 = -1e30f;
    #pragma unroll
    for (int n = 0; n < 4; n++) {
        m0 = fmaxf(m0, fmaxf(acc[n][0], acc[n][1]));
        m1 = fmaxf(m1, fmaxf(acc[n][2], acc[n][3]));
    }
    m0 = fmaxf(m0, __shfl_xor_sync(0xffffffffu, m0, 1));
    m0 = fmaxf(m0, __shfl_xor_sync(0xffffffffu, m0, 2));
    m1 = fmaxf(m1, __shfl_xor_sync(0xffffffffu, m1, 1));
    m1 = fmaxf(m1, __shfl_xor_sync(0xffffffffu, m1, 2));
    if (ti == 0) {
        pmax[warp * 16 + gi]     = m0;
        pmax[warp * 16 + 8 + gi] = m1;
    }
    __syncthreads();    // B1

    m0 = fmaxf(m0, pmax[pw * 16 + gi]);
    m1 = fmaxf(m1, pmax[pw * 16 + 8 + gi]);
    float s0 = 0.f, s1 = 0.f;
    #pragma unroll
    for (int n = 0; n < 4; n++) {
        acc[n][0] = __expf(acc[n][0] - m0);
        acc[n][1] = __expf(acc[n][1] - m0);
        acc[n][2] = __expf(acc[n][2] - m1);
        acc[n][3] = __expf(acc[n][3] - m1);
        s0 += acc[n][0] + acc[n][1];
        s1 += acc[n][2] + acc[n][3];
    }
    s0 += __shfl_xor_sync(0xffffffffu, s0, 1);
    s0 += __shfl_xor_sync(0xffffffffu, s0, 2);
    s1 += __shfl_xor_sync(0xffffffffu, s1, 1);
    s1 += __shfl_xor_sync(0xffffffffu, s1, 2);
    if (ti == 0) {
        psum[warp * 16 + gi]     = s0;
        psum[warp * 16 + 8 + gi] = s1;
    }

    // split exp (registers) -> PA planes [row][kpair]
    {
        int cp = (wn >> 1) + ti;
        #pragma unroll
        for (int n = 0; n < 4; n++) {
            unsigned h, l;
            int o0 = PLW(wm + gi, cp + n * 4);
            bsplit(acc[n][0], acc[n][1], h, l);
            PAh[o0] = h; PAl[o0] = l;
            int o1 = PLW(wm + gi + 8, cp + n * 4);
            bsplit(acc[n][2], acc[n][3], h, l);
            PAh[o1] = h; PAl[o1] = l;
        }
    }
    // V1 gather -> PB planes [k][dpair]
    #pragma unroll
    for (int it = 0; it < 4; it++) {
        int i4 = tid + it * 256;
        int k = i4 >> 4, c = (i4 & 15) << 2;
        float4 v = *(const float4*)(V1b + si1[k] * D_ + c);
        unsigned h0, l0, h1, l1;
        bsplit(v.x, v.y, h0, l0);
        bsplit(v.z, v.w, h1, l1);
        int off = PLW(k, c >> 1);
        *(uint2*)&PBh[off] = make_uint2(h0, h1);
        *(uint2*)&PBl[off] = make_uint2(l0, l1);
    }
    __syncthreads();    // B2

    const float inv0 = __frcp_rn(s0 + psum[pw * 16 + gi]);
    const float inv1 = __frcp_rn(s1 + psum[pw * 16 + 8 + gi]);

    // mm2: W[j][d] = inv[j] * sum_k exp[j][k] * V1g[k][d]
    #pragma unroll
    for (int n = 0; n < 4; n++)
        #pragma unroll
        for (int i = 0; i < 4; i++) acc[n][i] = 0.f;
    #pragma unroll
    for (int kc = 0; kc < 4; kc++) {
        unsigned ah[4], al[4], bhv[8], blv[8];
        unsigned offA = ((rA << 5) + (((2*kc + (mi >> 1)) ^ l7) << 2)) << 2;
        ldsm4(uPAh + offA, ah[0], ah[1], ah[2], ah[3]);
        ldsm4(uPAl + offA, al[0], al[1], al[2], al[3]);
        int k0 = kc * 16;
        int cb2 = (wn >> 3) + (mi >> 1);
        unsigned offB0 = (((k0 + rB2) << 5) + ((cb2 ^ l7) << 2)) << 2;
        unsigned offB1 = (((k0 + rB2) << 5) + (((cb2 + 2) ^ l7) << 2)) << 2;
        ldsm4t(uPBh + offB0, bhv[0], bhv[1], bhv[2], bhv[3]);
        ldsm4t(uPBh + offB1, bhv[4], bhv[5], bhv[6], bhv[7]);
        ldsm4t(uPBl + offB0, blv[0], blv[1], blv[2], blv[3]);
        ldsm4t(uPBl + offB1, blv[4], blv[5], blv[6], blv[7]);
        #pragma unroll
        for (int nt = 0; nt < 4; nt++) {
            bmma(acc[nt], ah, bhv[2*nt], bhv[2*nt+1]);
            bmma(acc[nt], ah, blv[2*nt], blv[2*nt+1]);
            bmma(acc[nt], al, bhv[2*nt], bhv[2*nt+1]);
        }
    }
    __syncthreads();    // B3: all mm2 reads of PA done

    // W (fp32, swizzled pairs) -> PA region
    float* Wb = (float*)PAh;
    #pragma unroll
    for (int nt = 0; nt < 4; nt++) {
        int pr = (wn >> 1) + nt * 4 + ti;
        *(float2*)&Wb[WIDX(wm + gi, pr)] =
            make_float2(acc[nt][0] * inv0, acc[nt][1] * inv0);
        *(float2*)&Wb[WIDX(wm + gi + 8, pr)] =
            make_float2(acc[nt][2] * inv1, acc[nt][3] * inv1);
    }
    __syncthreads();    // B4

    // out[d] = sum_j W[j][d] * V0g[j][d]
    {
        int d  = tid & 63;
        int jg = tid >> 6;             // 0..3
        int dp = d >> 1, db = d & 1;
        float s = 0.f;
        #pragma unroll
        for (int jj = 0; jj < 16; jj++) {
            int j = jg * 16 + jj;
            s += Wb[WIDX(j, dp) + db] * V0b[si0[j] * D_ + d];
        }
        part[jg * 64 + d] = s;
        __syncthreads();
        if (tid < 64) {
            float o = part[tid] + part[64 + tid] + part[128 + tid] + part[192 + tid];
            int b = bh >> 3, h = bh & 7;
            g_ctx[(b * T_ + t) * HD_ + h * D_ + tid] = o;
        }
    }
}

// ---------------------------------------------------------------------------
// 4) out = ctx @ Wo.  64x64 tile, split-K=2 (atomicAdd), grid (8,16,2).
// ---------------------------------------------------------------------------
#define OASTR 68
__global__ __launch_bounds__(256)
void out_kernel(const float* __restrict__ Wo, float* __restrict__ out)
{
    const int n0 = blockIdx.x * 64;
    const int m0 = blockIdx.y * 64;
    const int kbase = blockIdx.z * 256;
    const int tid = threadIdx.x;
    const int tx = tid & 15, ty = tid >> 4;

    __shared__ float As[16][OASTR];
    __shared__ float Bs[16][64];

    const int am = tid >> 2, akp = (tid & 3) * 4;
    const int brow = tid >> 4, bch = (tid & 15) * 4;

    float acc[4][4];
    #pragma unroll
    for (int i = 0; i < 4; i++)
        #pragma unroll
        for (int j = 0; j < 4; j++) acc[i][j] = 0.f;

    float4 ra = *(const float4*)(g_ctx + (m0 + am) * HD_ + kbase + akp);
    float4 rb = *(const float4*)(Wo + (kbase + brow) * E_ + n0 + bch);

    for (int k0 = kbase; k0 < kbase + 256; k0 += 16) {
        As[akp + 0][am] = ra.x; As[akp + 1][am] = ra.y;
        As[akp + 2][am] = ra.z; As[akp + 3][am] = ra.w;
        *(float4*)&Bs[brow][bch] = rb;
        __syncthreads();
        if (k0 + 16 < kbase + 256) {
            ra = *(const float4*)(g_ctx + (m0 + am) * HD_ + k0 + 16 + akp);
            rb = *(const float4*)(Wo + (k0 + 16 + brow) * E_ + n0 + bch);
        }
        #pragma unroll
        for (int kk = 0; kk < 16; kk++) {
            float4 av = *(const float4*)&As[kk][ty * 4];
            float4 bv = *(const float4*)&Bs[kk][tx * 4];
            float a[4] = {av.x, av.y, av.z, av.w};
            float b[4] = {bv.x, bv.y, bv.z, bv.w};
            #pragma unroll
            for (int i = 0; i < 4; i++)
                #pragma unroll
                for (int j = 0; j < 4; j++) acc[i][j] += a[i] * b[j];
        }
        __syncthreads();
    }
    #pragma unroll
    for (int i = 0; i < 4; i++) {
        float* row = out + (m0 + ty * 4 + i) * E_ + n0 + tx * 4;
        #pragma unroll
        for (int j = 0; j < 4; j++)
            atomicAdd(row + j, acc[i][j]);
    }
}

// ---------------------------------------------------------------------------
extern "C" void kernel_launch(void* const* d_in, const int* in_sizes, int n_in,
                              void* d_out, int out_size)
{
    const float* x  = (const float*)d_in[0];
    const float* Wq = (const float*)d_in[1];
    const float* Wk = (const float*)d_in[2];
    const float* Wv = (const float*)d_in[3];
    const float* Wo = (const float*)d_in[4];
    float* out = (float*)d_out;

    cudaFuncSetAttribute(attn_kernel,
                         cudaFuncAttributeMaxDynamicSharedMemorySize, ATT_SMEM);

    dim3 gProj(40, 8);
    proj_kernel<<<gProj, 256>>>(x, Wq, Wk, Wv);

    dim3 gLog(20, 32);
    logits_kernel<<<gLog, 256>>>();

    dim3 gSel(T_, BH_, 2);
    select_kernel<<<gSel, 256>>>();

    dim3 gAtt(T_, BH_);
    attn_kernel<<<gAtt, 256, ATT_SMEM>>>();

    int nquads = out_size / 4;
    zero_kernel<<<(nquads + 255) / 256, 256>>>(out, nquads);

    dim3 gOut(E_ / 64, M_ / 64, 2);
    out_kernel<<<gOut, 256>>>(Wo, out);
}